// round 11
// baseline (speedup 1.0000x reference)
#include <cuda_runtime.h>

#define BATCH 32
#define N4 262144             // float4 rows per batch
#define NG 4                  // pipeline groups
#define GB 8                  // batches per group
#define SUBB 32               // blocks cooperating on one batch
#define THREADS 256
#define STRIDE (SUBB * THREADS)          // 8192
#define RITERS (N4 / STRIDE)             // 32
#define LB 16
#define RCHUNKS (RITERS / LB)            // 2
#define OUT4 65536
#define OITERS (OUT4 / STRIDE)           // 8

__device__ double g_part[BATCH][SUBB][14];
__device__ float  g_coef[BATCH][8];
__device__ int    g_cnt1[BATCH];
__device__ int    g_cnt2[BATCH];
__device__ int    g_flag[BATCH];

__device__ __forceinline__ void phase1(const float4* __restrict__ xb, int b,
                                       int sub, int tid) {
    float a0=0.f,a1=0.f,a2=0.f,a3=0.f;
    float q00=0.f,q01=0.f,q02=0.f,q03=0.f;
    float q11=0.f,q12=0.f,q13=0.f;
    float q22=0.f,q23=0.f,q33=0.f;

    int base = sub * THREADS + tid;
    for (int ch = 0; ch < RCHUNKS; ch++) {
        float4 vbuf[LB];
        #pragma unroll
        for (int j = 0; j < LB; j++)
            vbuf[j] = __ldg(&xb[base + (ch * LB + j) * STRIDE]);
        #pragma unroll
        for (int j = 0; j < LB; j++) {
            float4 v = vbuf[j];
            a0 += v.x; a1 += v.y; a2 += v.z; a3 += v.w;
            q00 = fmaf(v.x, v.x, q00);
            q01 = fmaf(v.x, v.y, q01);
            q02 = fmaf(v.x, v.z, q02);
            q03 = fmaf(v.x, v.w, q03);
            q11 = fmaf(v.y, v.y, q11);
            q12 = fmaf(v.y, v.z, q12);
            q13 = fmaf(v.y, v.w, q13);
            q22 = fmaf(v.z, v.z, q22);
            q23 = fmaf(v.z, v.w, q23);
            q33 = fmaf(v.w, v.w, q33);
        }
    }

    float acc[14] = {a0,a1,a2,a3,q00,q01,q02,q03,q11,q12,q13,q22,q23,q33};
    #pragma unroll
    for (int k = 0; k < 14; k++) {
        #pragma unroll
        for (int off = 16; off > 0; off >>= 1)
            acc[k] += __shfl_down_sync(0xffffffffu, acc[k], off);
    }

    __shared__ double sh[8][14];
    int warp = tid >> 5;
    int lane = tid & 31;
    if (lane == 0) {
        #pragma unroll
        for (int k = 0; k < 14; k++) sh[warp][k] = (double)acc[k];
    }
    __syncthreads();

    if (tid < 14) {
        double s = 0.0;
        #pragma unroll
        for (int w = 0; w < 8; w++) s += sh[w][tid];
        g_part[b][sub][tid] = s;
    }
    __threadfence();
    __syncthreads();

    __shared__ int is_last;
    if (tid == 0)
        is_last = (atomicAdd(&g_cnt1[b], 1) == SUBB - 1) ? 1 : 0;
    __syncthreads();

    if (is_last && tid == 0) {
        double S[14];
        #pragma unroll
        for (int k = 0; k < 14; k++) {
            double s = 0.0;
            for (int w = 0; w < SUBB; w++) s += g_part[b][w][k];
            S[k] = s;
        }

        const double N = (double)N4;
        double m[4];
        #pragma unroll
        for (int j = 0; j < 4; j++) m[j] = S[j] / N;

        double Q[4][4];
        Q[0][0]=S[4];  Q[0][1]=S[5];  Q[0][2]=S[6];  Q[0][3]=S[7];
        Q[1][1]=S[8];  Q[1][2]=S[9];  Q[1][3]=S[10];
        Q[2][2]=S[11]; Q[2][3]=S[12]; Q[3][3]=S[13];
        Q[1][0]=Q[0][1]; Q[2][0]=Q[0][2]; Q[3][0]=Q[0][3];
        Q[2][1]=Q[1][2]; Q[3][1]=Q[1][3]; Q[3][2]=Q[2][3];

        double inv_s[4];
        #pragma unroll
        for (int j = 0; j < 4; j++) {
            double var = Q[j][j] / N - m[j] * m[j];
            inv_s[j] = (var > 0.0) ? 1.0 / sqrt(var) : 0.0;
        }

        float A[4][4];
        #pragma unroll
        for (int i = 0; i < 4; i++)
            #pragma unroll
            for (int j = 0; j < 4; j++) {
                double aij = (Q[i][j] - N * m[i] * m[j]) * inv_s[i] * inv_s[j];
                A[i][j] = (float)(i == j ? aij - 1.0 : aij);
            }

        float V[4][4] = {{1,0,0,0},{0,1,0,0},{0,0,1,0},{0,0,0,1}};
        for (int sweep = 0; sweep < 6; sweep++) {
            float offsum = fabsf(A[0][1]) + fabsf(A[0][2]) + fabsf(A[0][3])
                         + fabsf(A[1][2]) + fabsf(A[1][3]) + fabsf(A[2][3]);
            if (offsum == 0.0f) break;
            for (int p = 0; p < 3; p++) {
                for (int q = p + 1; q < 4; q++) {
                    float apq = A[p][q];
                    if (apq == 0.0f) continue;
                    float theta = (A[q][q] - A[p][p]) / (2.0f * apq);
                    float tt = copysignf(1.0f, theta) / (fabsf(theta) + sqrtf(theta * theta + 1.0f));
                    float c = rsqrtf(tt * tt + 1.0f);
                    float s = tt * c;
                    float tau = s / (1.0f + c);
                    for (int r = 0; r < 4; r++) {
                        if (r == p || r == q) continue;
                        float g = A[r][p], h = A[r][q];
                        A[r][p] = A[p][r] = g - s * (h + tau * g);
                        A[r][q] = A[q][r] = h + s * (g - tau * h);
                    }
                    A[p][p] -= tt * apq;
                    A[q][q] += tt * apq;
                    A[p][q] = A[q][p] = 0.0f;
                    for (int r = 0; r < 4; r++) {
                        float g = V[r][p], h = V[r][q];
                        V[r][p] = g - s * (h + tau * g);
                        V[r][q] = h + s * (g - tau * h);
                    }
                }
            }
        }

        int k = 0;
        float best = A[0][0];
        #pragma unroll
        for (int j = 1; j < 4; j++) if (A[j][j] > best) { best = A[j][j]; k = j; }

        double v[4];
        #pragma unroll
        for (int j = 0; j < 4; j++) v[j] = (double)V[j][k];
        double sv = v[0] + v[1] + v[2] + v[3];
        if (sv < 0.0) {
            #pragma unroll
            for (int j = 0; j < 4; j++) v[j] = -v[j];
        }

        double w[4], off = 0.0;
        #pragma unroll
        for (int j = 0; j < 4; j++) {
            w[j] = v[j] * inv_s[j];
            off += w[j] * m[j];
        }

        g_coef[b][0] = (float)w[0];
        g_coef[b][1] = (float)w[1];
        g_coef[b][2] = (float)w[2];
        g_coef[b][3] = (float)w[3];
        g_coef[b][4] = (float)off;

        __threadfence();
        atomicExch(&g_flag[b], 1);
    }
}

__device__ __forceinline__ void phase2(const float4* __restrict__ xb,
                                       float4* __restrict__ ob, int b,
                                       int sub, int tid) {
    if (tid == 0) {
        while (*(volatile int*)&g_flag[b] == 0) __nanosleep(32);
    }
    __syncthreads();
    __threadfence();

    float w0 = g_coef[b][0];
    float w1 = g_coef[b][1];
    float w2 = g_coef[b][2];
    float w3 = g_coef[b][3];
    float off = g_coef[b][4];

    int base = sub * THREADS + tid;
    #pragma unroll
    for (int it = 0; it < OITERS; it++) {
        int j = base + it * STRIDE;
        int c4 = j & 15;
        int ow = (j >> 4) & 63;
        int oh = j >> 10;
        int h = (oh << 1) | (c4 >> 3);
        int w = (ow << 1) | ((c4 >> 2) & 1);
        int ib = (h << 11) | (w << 4) | ((c4 & 3) << 2);

        float4 v0 = __ldg(&xb[ib + 0]);
        float4 v1 = __ldg(&xb[ib + 1]);
        float4 v2 = __ldg(&xb[ib + 2]);
        float4 v3 = __ldg(&xb[ib + 3]);

        float4 r;
        r.x = fmaf(v0.x, w0, fmaf(v0.y, w1, fmaf(v0.z, w2, fmaf(v0.w, w3, -off))));
        r.y = fmaf(v1.x, w0, fmaf(v1.y, w1, fmaf(v1.z, w2, fmaf(v1.w, w3, -off))));
        r.z = fmaf(v2.x, w0, fmaf(v2.y, w1, fmaf(v2.z, w2, fmaf(v2.w, w3, -off))));
        r.w = fmaf(v3.x, w0, fmaf(v3.y, w1, fmaf(v3.z, w2, fmaf(v3.w, w3, -off))));
        ob[j] = r;
    }

    __syncthreads();
    if (tid == 0) {
        __threadfence();
        if (atomicAdd(&g_cnt2[b], 1) == SUBB - 1) {
            g_cnt1[b] = 0;
            g_flag[b] = 0;
            g_cnt2[b] = 0;
        }
    }
}

__global__ void __launch_bounds__(THREADS, 2) fused_kernel(const float4* __restrict__ x,
                                                           float4* __restrict__ out) {
    int big = blockIdx.x >> 5;         // batch within group (0..7)
    int sub = blockIdx.x & (SUBB - 1); // sub-block within batch (0..31)
    int tid = threadIdx.x;

    // pipeline: P1(g); P2(g-1). Adjacent-stage working set ~64MB < L2.
    for (int g = 0; g < NG; g++) {
        int b = g * GB + big;
        phase1(x + (size_t)b * N4, b, sub, tid);
        if (g > 0) {
            int bp = (g - 1) * GB + big;
            phase2(x + (size_t)bp * N4, out + (size_t)bp * OUT4, bp, sub, tid);
        }
    }
    {
        int bp = (NG - 1) * GB + big;
        phase2(x + (size_t)bp * N4, out + (size_t)bp * OUT4, bp, sub, tid);
    }
}

extern "C" void kernel_launch(void* const* d_in, const int* in_sizes, int n_in,
                              void* d_out, int out_size) {
    const float4* x = (const float4*)d_in[0];
    float4* out = (float4*)d_out;

    fused_kernel<<<GB * SUBB, THREADS>>>(x, out);
}

// round 12
// speedup vs baseline: 2.8632x; 2.8632x over previous
#include <cuda_runtime.h>

#define BATCH 32
#define N4 262144            // float4 rows per batch = 128*128*64/4
#define PB 8                 // blocks per batch (grid = 256; 2/SM resident on 148 SMs)
#define THREADS 256
#define LB 16                // load batch (outstanding LDG.128 per warp)
#define RITERS (N4 / (PB * THREADS))        // 128
#define RCHUNKS (RITERS / LB)               // 8
#define OUT4 65536                          // output float4s per batch
#define OITERS (OUT4 / (PB * THREADS))      // 32

__device__ double g_part[BATCH][PB][14];
__device__ float  g_coef[BATCH][8];
__device__ int    g_cnt1[BATCH];
__device__ int    g_cnt2[BATCH];
__device__ int    g_flag[BATCH];

__device__ __forceinline__ void stcs(float4* p, float4 v) {
    asm volatile("st.global.cs.v4.f32 [%0], {%1, %2, %3, %4};"
                 :: "l"(p), "f"(v.x), "f"(v.y), "f"(v.z), "f"(v.w) : "memory");
}

__global__ void __launch_bounds__(THREADS, 2) fused_kernel(const float4* __restrict__ x,
                                                           float4* __restrict__ out) {
    int b   = blockIdx.x >> 3;
    int blk = blockIdx.x & (PB - 1);
    int tid = threadIdx.x;

    const float4* __restrict__ xb = x + (size_t)b * N4;

    // ───────── phase 1: moment reduction, 16-deep load batches, front-to-back ─────────
    float a0=0.f,a1=0.f,a2=0.f,a3=0.f;
    float q00=0.f,q01=0.f,q02=0.f,q03=0.f;
    float q11=0.f,q12=0.f,q13=0.f;
    float q22=0.f,q23=0.f,q33=0.f;

    int base = blk * THREADS + tid;
    for (int ch = 0; ch < RCHUNKS; ch++) {
        float4 vbuf[LB];
        #pragma unroll
        for (int j = 0; j < LB; j++)
            vbuf[j] = __ldg(&xb[base + (ch * LB + j) * (PB * THREADS)]);
        #pragma unroll
        for (int j = 0; j < LB; j++) {
            float4 v = vbuf[j];
            a0 += v.x; a1 += v.y; a2 += v.z; a3 += v.w;
            q00 = fmaf(v.x, v.x, q00);
            q01 = fmaf(v.x, v.y, q01);
            q02 = fmaf(v.x, v.z, q02);
            q03 = fmaf(v.x, v.w, q03);
            q11 = fmaf(v.y, v.y, q11);
            q12 = fmaf(v.y, v.z, q12);
            q13 = fmaf(v.y, v.w, q13);
            q22 = fmaf(v.z, v.z, q22);
            q23 = fmaf(v.z, v.w, q23);
            q33 = fmaf(v.w, v.w, q33);
        }
    }

    float acc[14] = {a0,a1,a2,a3,q00,q01,q02,q03,q11,q12,q13,q22,q23,q33};

    #pragma unroll
    for (int k = 0; k < 14; k++) {
        #pragma unroll
        for (int off = 16; off > 0; off >>= 1)
            acc[k] += __shfl_down_sync(0xffffffffu, acc[k], off);
    }

    __shared__ double sh[8][14];
    int warp = tid >> 5;
    int lane = tid & 31;
    if (lane == 0) {
        #pragma unroll
        for (int k = 0; k < 14; k++) sh[warp][k] = (double)acc[k];
    }
    __syncthreads();

    if (tid < 14) {
        double s = 0.0;
        #pragma unroll
        for (int w = 0; w < 8; w++) s += sh[w][tid];
        g_part[b][blk][tid] = s;
    }

    __threadfence();
    __syncthreads();

    __shared__ int is_last;
    if (tid == 0)
        is_last = (atomicAdd(&g_cnt1[b], 1) == PB - 1) ? 1 : 0;
    __syncthreads();

    // ───────── last block of this batch: 4x4 solve, publish coefs ─────────
    if (is_last && tid == 0) {
        double S[14];
        #pragma unroll
        for (int k = 0; k < 14; k++) {
            double s = 0.0;
            #pragma unroll
            for (int w = 0; w < PB; w++) s += g_part[b][w][k];
            S[k] = s;
        }

        const double N = (double)N4;
        double m[4];
        #pragma unroll
        for (int j = 0; j < 4; j++) m[j] = S[j] / N;

        double Q[4][4];
        Q[0][0]=S[4];  Q[0][1]=S[5];  Q[0][2]=S[6];  Q[0][3]=S[7];
        Q[1][1]=S[8];  Q[1][2]=S[9];  Q[1][3]=S[10];
        Q[2][2]=S[11]; Q[2][3]=S[12]; Q[3][3]=S[13];
        Q[1][0]=Q[0][1]; Q[2][0]=Q[0][2]; Q[3][0]=Q[0][3];
        Q[2][1]=Q[1][2]; Q[3][1]=Q[1][3]; Q[3][2]=Q[2][3];

        double inv_s[4];
        #pragma unroll
        for (int j = 0; j < 4; j++) {
            double var = Q[j][j] / N - m[j] * m[j];
            inv_s[j] = (var > 0.0) ? 1.0 / sqrt(var) : 0.0;
        }

        float A[4][4];
        #pragma unroll
        for (int i = 0; i < 4; i++)
            #pragma unroll
            for (int j = 0; j < 4; j++) {
                double aij = (Q[i][j] - N * m[i] * m[j]) * inv_s[i] * inv_s[j];
                A[i][j] = (float)(i == j ? aij - 1.0 : aij);
            }

        float V[4][4] = {{1,0,0,0},{0,1,0,0},{0,0,1,0},{0,0,0,1}};
        for (int sweep = 0; sweep < 6; sweep++) {
            float offsum = fabsf(A[0][1]) + fabsf(A[0][2]) + fabsf(A[0][3])
                         + fabsf(A[1][2]) + fabsf(A[1][3]) + fabsf(A[2][3]);
            if (offsum == 0.0f) break;
            for (int p = 0; p < 3; p++) {
                for (int q = p + 1; q < 4; q++) {
                    float apq = A[p][q];
                    if (apq == 0.0f) continue;
                    float theta = (A[q][q] - A[p][p]) / (2.0f * apq);
                    float tt = copysignf(1.0f, theta) / (fabsf(theta) + sqrtf(theta * theta + 1.0f));
                    float c = rsqrtf(tt * tt + 1.0f);
                    float s = tt * c;
                    float tau = s / (1.0f + c);
                    for (int r = 0; r < 4; r++) {
                        if (r == p || r == q) continue;
                        float g = A[r][p], h = A[r][q];
                        A[r][p] = A[p][r] = g - s * (h + tau * g);
                        A[r][q] = A[q][r] = h + s * (g - tau * h);
                    }
                    A[p][p] -= tt * apq;
                    A[q][q] += tt * apq;
                    A[p][q] = A[q][p] = 0.0f;
                    for (int r = 0; r < 4; r++) {
                        float g = V[r][p], h = V[r][q];
                        V[r][p] = g - s * (h + tau * g);
                        V[r][q] = h + s * (g - tau * h);
                    }
                }
            }
        }

        int k = 0;
        float best = A[0][0];
        #pragma unroll
        for (int j = 1; j < 4; j++) if (A[j][j] > best) { best = A[j][j]; k = j; }

        double v[4];
        #pragma unroll
        for (int j = 0; j < 4; j++) v[j] = (double)V[j][k];
        double sv = v[0] + v[1] + v[2] + v[3];
        if (sv < 0.0) {
            #pragma unroll
            for (int j = 0; j < 4; j++) v[j] = -v[j];
        }

        double w[4], off = 0.0;
        #pragma unroll
        for (int j = 0; j < 4; j++) {
            w[j] = v[j] * inv_s[j];
            off += w[j] * m[j];
        }

        g_coef[b][0] = (float)w[0];
        g_coef[b][1] = (float)w[1];
        g_coef[b][2] = (float)w[2];
        g_coef[b][3] = (float)w[3];
        g_coef[b][4] = (float)off;

        __threadfence();
        atomicExch(&g_flag[b], 1);   // release
    }

    // ───────── phase 2: wait for coefs, then write output READING INPUT IN REVERSE ─────────
    // L2 holds the most-recently-streamed tail of the input; reading newest-first
    // converts most phase-2 reads into L2 hits (forward order = LRU worst case).
    if (tid == 0) {
        while (*(volatile int*)&g_flag[b] == 0) __nanosleep(64);
    }
    __syncthreads();
    __threadfence();   // acquire

    float w0 = g_coef[b][0];
    float w1 = g_coef[b][1];
    float w2 = g_coef[b][2];
    float w3 = g_coef[b][3];
    float off = g_coef[b][4];

    float4* __restrict__ ob = out + (size_t)b * OUT4;

    #pragma unroll 4
    for (int it = OITERS - 1; it >= 0; it--) {
        int j = base + it * (PB * THREADS);
        int c4 = j & 15;
        int ow = (j >> 4) & 63;
        int oh = j >> 10;
        int h = (oh << 1) | (c4 >> 3);
        int w = (ow << 1) | ((c4 >> 2) & 1);
        int ib = (h << 11) | (w << 4) | ((c4 & 3) << 2);

        float4 v0 = __ldg(&xb[ib + 0]);
        float4 v1 = __ldg(&xb[ib + 1]);
        float4 v2 = __ldg(&xb[ib + 2]);
        float4 v3 = __ldg(&xb[ib + 3]);

        float4 r;
        r.x = fmaf(v0.x, w0, fmaf(v0.y, w1, fmaf(v0.z, w2, fmaf(v0.w, w3, -off))));
        r.y = fmaf(v1.x, w0, fmaf(v1.y, w1, fmaf(v1.z, w2, fmaf(v1.w, w3, -off))));
        r.z = fmaf(v2.x, w0, fmaf(v2.y, w1, fmaf(v2.z, w2, fmaf(v2.w, w3, -off))));
        r.w = fmaf(v3.x, w0, fmaf(v3.y, w1, fmaf(v3.z, w2, fmaf(v3.w, w3, -off))));
        stcs(&ob[j], r);   // evict-first: don't let output lines push input out of L2
    }

    // ───────── cleanup: last phase-2 block of each batch resets state ─────────
    __syncthreads();
    if (tid == 0) {
        __threadfence();
        if (atomicAdd(&g_cnt2[b], 1) == PB - 1) {
            g_cnt1[b] = 0;
            g_flag[b] = 0;
            g_cnt2[b] = 0;
        }
    }
}

extern "C" void kernel_launch(void* const* d_in, const int* in_sizes, int n_in,
                              void* d_out, int out_size) {
    const float4* x = (const float4*)d_in[0];
    float4* out = (float4*)d_out;

    fused_kernel<<<BATCH * PB, THREADS>>>(x, out);
}